// round 11
// baseline (speedup 1.0000x reference)
#include <cuda_runtime.h>
#include <cuda_bf16.h>
#include <mma.h>
#include <cstdint>

using namespace nvcuda;

#define FULL_MASK 0xFFFFFFFFu
typedef unsigned long long ull;

// split fp32 pair -> bf16 hi pair + bf16 lo pair (packed u32 each)
__device__ __forceinline__ void split2(float v0, float v1, uint32_t& h, uint32_t& l) {
    uint32_t hh;
    asm("cvt.rn.bf16x2.f32 %0, %1, %2;" : "=r"(hh) : "f"(v1), "f"(v0));
    const float h0 = __uint_as_float(hh << 16);
    const float h1 = __uint_as_float(hh & 0xFFFF0000u);
    uint32_t ll;
    asm("cvt.rn.bf16x2.f32 %0, %1, %2;" : "=r"(ll) : "f"(v1 - h1), "f"(v0 - h0));
    h = hh; l = ll;
}

// ---------------- model constants ----------------
__constant__ int FOFF[23] = {0,4,8,12,16,20,24,28,32,36,40,44,48,50,52,53,57,58,59,60,61,62,63};
__constant__ int FDIM[23] = {4,4,4,4,4,4,4,4,4,4,4,4, 2, 2, 1, 4, 1, 1, 1, 1, 1, 1, 2};

static constexpr int OBS  = 65;
static constexpr int NF   = 23;
static constexpr int ZDIM = 230;
static constexpr int HID  = 164;
static constexpr int BATCH = 131072;
static constexpr int ZS   = 232;
static constexpr int NP   = 176;     // padded N for wmma (11 tiles of 16)

__device__ __align__(16) float g_wh[6 * 168];
__device__ float g_bh[6];
__device__ __align__(16) float g_wproj[NF * 10 * 4];
__device__ __align__(16) float g_wqkv[10 * 32];
__device__ int g_offadj[32];
__device__ float g_z[(size_t)BATCH * ZS];
// bf16 hi/lo weight blobs, row-major [K_pad][176]; bias folded at k=K_real
// L1: 2 x 240*176*2 = 2 x 84480 B ; L2-5: 2 x 176*176*2 = 2 x 61952 B
__device__ __align__(16) unsigned char g_wb[664576];

__host__ __device__ __forceinline__ int wb_off(int l) {
    return (l == 0) ? 0 : 168960 + (l - 1) * 123904;
}
__host__ __device__ __forceinline__ int wb_half(int l) {
    return (l == 0) ? 84480 : 61952;
}

// ======================= pack: phase1 weights + heads ===================
__global__ void pack_misc(
    const float* __restrict__ Wm, const float* __restrict__ bm,
    const float* __restrict__ Wmk, const float* __restrict__ bmk,
    const float* __restrict__ Wp,
    const float* __restrict__ Wq, const float* __restrict__ Wk,
    const float* __restrict__ Wv)
{
    const int k = blockIdx.x;   // 0..231
    const int l = blockIdx.y;   // 0..2
    const int c = threadIdx.x;  // 0..191
    if (l == 0) {
        if (k >= 168 || c >= 6) return;
        g_wh[c * 168 + k] = (k < HID) ? ((c < 5) ? Wm[k * 5 + c] : Wmk[k]) : 0.f;
        if (k == 0) g_bh[c] = (c < 5) ? bm[c] : bmk[0];
    } else if (l == 1) {
        if (k < ZDIM && c < 4) {
            const int i = k / 10;
            const int off  = FOFF[i];
            const int dim  = FDIM[i];
            const int offa = (off < 61) ? off : 61;
            const int shift = off - offa;
            float v = 0.f;
            if (c >= shift && (c - shift) < dim) v = Wp[(offa + c) * ZDIM + k];
            g_wproj[k * 4 + c] = v;
        }
        if (c == 4 && k < 32)
            g_offadj[k] = (k < NF) ? ((FOFF[k] < 61) ? FOFF[k] : 61) : 0;
    } else {
        if (k < 10 && c < 32) {
            float v = 0.f;
            if (c < 10)      v = Wq[k * 10 + c];
            else if (c < 20) v = Wk[k * 10 + (c - 10)];
            else if (c < 30) v = Wv[k * 10 + (c - 20)];
            g_wqkv[k * 32 + c] = v;
        }
    }
}

// ======================= pack: MLP weight blobs (bf16 hi/lo) ============
__global__ void pack_wb(
    const float* __restrict__ W1, const float* __restrict__ W2,
    const float* __restrict__ W3, const float* __restrict__ W4,
    const float* __restrict__ W5,
    const float* __restrict__ b1, const float* __restrict__ b2,
    const float* __restrict__ b3, const float* __restrict__ b4,
    const float* __restrict__ b5)
{
    const int k = blockIdx.x;          // 0..239
    const int l = blockIdx.y >> 1;     // 0..4
    const int h = blockIdx.y & 1;      // 0 hi, 1 lo
    const int n = threadIdx.x;         // 0..175
    const int kalloc = (l == 0) ? 240 : 176;
    if (k >= kalloc) return;
    const int kreal = (l == 0) ? 230 : 164;
    const float* W = (l == 0) ? W1 : (l == 1) ? W2 : (l == 2) ? W3 : (l == 3) ? W4 : W5;
    const float* b = (l == 0) ? b1 : (l == 1) ? b2 : (l == 2) ? b3 : (l == 3) ? b4 : b5;
    float w = 0.f;
    if (n < HID) {
        if (k < kreal)      w = W[k * HID + n];
        else if (k == kreal) w = b[n];
    }
    const __nv_bfloat16 bhi = __float2bfloat16(w);
    unsigned short bits;
    if (h == 0) bits = __bfloat16_as_ushort(bhi);
    else        bits = __bfloat16_as_ushort(__float2bfloat16(w - __bfloat162float(bhi)));
    *(unsigned short*)(g_wb + wb_off(l) + h * wb_half(l) + (k * NP + n) * 2) = bits;
}

// ======================= Phase 1: proj + attention (R8, unchanged) ======
__global__ void __launch_bounds__(256, 2)
phase1_kernel(const float* __restrict__ x, const float* __restrict__ bpj, int B)
{
    __shared__ float kvs[8][1152];
    const int tid  = threadIdx.x;
    const int w    = tid >> 5;
    const int lane = tid & 31;
    float* kb0 = kvs[w];
    float* vb0 = kvs[w] + 288;
    float* kb1 = kvs[w] + 576;
    float* vb1 = kvs[w] + 864;

    const float inv_sqrt10 = 0.31622776601683794f;
    const int tok = (lane < NF) ? lane : 0;
    const int offa = g_offadj[tok];
    float bq[10];
    {
        const float2* b2 = (const float2*)(bpj + tok * 10);
        #pragma unroll
        for (int u = 0; u < 5; u++) { float2 t = b2[u]; bq[2*u] = t.x; bq[2*u+1] = t.y; }
    }
    const int rowbase = blockIdx.x * 32 + w * 4;

    #pragma unroll 1
    for (int pass = 0; pass < 2; pass++) {
        const int row0 = rowbase + 2 * pass;
        const int row1 = row0 + 1;
        float* zrow0 = g_z + (size_t)row0 * ZS;
        float* zrow1 = g_z + (size_t)row1 * ZS;
        const float* xr0 = x + (long long)row0 * OBS + offa;
        const float* xr1 = x + (long long)row1 * OBS + offa;
        const float x00 = xr0[0], x01 = xr0[1], x02 = xr0[2], x03 = xr0[3];
        const float x10 = xr1[0], x11 = xr1[1], x12 = xr1[2], x13 = xr1[3];

        float h0[10], h1[10];
        #pragma unroll
        for (int e = 0; e < 10; e++) {
            const float4 wq = ((const float4*)g_wproj)[tok * 10 + e];
            h0[e] = fmaf(x03, wq.w, fmaf(x02, wq.z, fmaf(x01, wq.y, fmaf(x00, wq.x, bq[e]))));
            h1[e] = fmaf(x13, wq.w, fmaf(x12, wq.z, fmaf(x11, wq.y, fmaf(x10, wq.x, bq[e]))));
        }
        {
            float kk0[10], vv0[10], kk1[10], vv1[10];
            #pragma unroll
            for (int e = 0; e < 10; e++) { kk0[e]=0.f; vv0[e]=0.f; kk1[e]=0.f; vv1[e]=0.f; }
            #pragma unroll
            for (int d = 0; d < 10; d++) {
                float wf[24];
                #pragma unroll
                for (int u = 0; u < 6; u++)
                    *(float4*)(wf + 4 * u) = ((const float4*)(g_wqkv + d * 32))[2 + u];
                const float hd0 = h0[d], hd1 = h1[d];
                #pragma unroll
                for (int e = 0; e < 10; e++) {
                    kk0[e] = fmaf(hd0, wf[e + 2],  kk0[e]);
                    kk1[e] = fmaf(hd1, wf[e + 2],  kk1[e]);
                    vv0[e] = fmaf(hd0, wf[e + 12], vv0[e]);
                    vv1[e] = fmaf(hd1, wf[e + 12], vv1[e]);
                }
            }
            if (lane < NF) {
                float2* ks0 = (float2*)(kb0 + tok * 12);
                float2* vs0 = (float2*)(vb0 + tok * 12);
                float2* ks1 = (float2*)(kb1 + tok * 12);
                float2* vs1 = (float2*)(vb1 + tok * 12);
                #pragma unroll
                for (int u = 0; u < 5; u++) {
                    ks0[u] = make_float2(kk0[2*u], kk0[2*u+1]);
                    vs0[u] = make_float2(vv0[2*u], vv0[2*u+1]);
                    ks1[u] = make_float2(kk1[2*u], kk1[2*u+1]);
                    vs1[u] = make_float2(vv1[2*u], vv1[2*u+1]);
                }
            }
        }
        float q0[10], q1[10];
        #pragma unroll
        for (int e = 0; e < 10; e++) { q0[e] = 0.f; q1[e] = 0.f; }
        #pragma unroll
        for (int d = 0; d < 10; d++) {
            float wf[12];
            #pragma unroll
            for (int u = 0; u < 3; u++)
                *(float4*)(wf + 4 * u) = ((const float4*)(g_wqkv + d * 32))[u];
            const float hd0 = h0[d], hd1 = h1[d];
            #pragma unroll
            for (int e = 0; e < 10; e++) {
                q0[e] = fmaf(hd0, wf[e], q0[e]);
                q1[e] = fmaf(hd1, wf[e], q1[e]);
            }
        }
        __syncwarp();

        float ssum0 = 0.f, ssum1 = 0.f;
        float ctx0[10], ctx1[10];
        #pragma unroll
        for (int e = 0; e < 10; e++) { ctx0[e] = 0.f; ctx1[e] = 0.f; }
        #pragma unroll 1
        for (int j = 0; j < NF; j++) {
            const float* kj0 = kb0 + j * 12;
            const float4 ka0 = *(const float4*)kj0;
            const float4 kb0v = *(const float4*)(kj0 + 4);
            const float2 kc0 = *(const float2*)(kj0 + 8);
            const float* kj1 = kb1 + j * 12;
            const float4 ka1 = *(const float4*)kj1;
            const float4 kb1v = *(const float4*)(kj1 + 4);
            const float2 kc1 = *(const float2*)(kj1 + 8);
            float dt0 = q0[0] * ka0.x;
            float dt1 = q1[0] * ka1.x;
            dt0 = fmaf(q0[1], ka0.y, dt0);  dt1 = fmaf(q1[1], ka1.y, dt1);
            dt0 = fmaf(q0[2], ka0.z, dt0);  dt1 = fmaf(q1[2], ka1.z, dt1);
            dt0 = fmaf(q0[3], ka0.w, dt0);  dt1 = fmaf(q1[3], ka1.w, dt1);
            dt0 = fmaf(q0[4], kb0v.x, dt0); dt1 = fmaf(q1[4], kb1v.x, dt1);
            dt0 = fmaf(q0[5], kb0v.y, dt0); dt1 = fmaf(q1[5], kb1v.y, dt1);
            dt0 = fmaf(q0[6], kb0v.z, dt0); dt1 = fmaf(q1[6], kb1v.z, dt1);
            dt0 = fmaf(q0[7], kb0v.w, dt0); dt1 = fmaf(q1[7], kb1v.w, dt1);
            dt0 = fmaf(q0[8], kc0.x, dt0);  dt1 = fmaf(q1[8], kc1.x, dt1);
            dt0 = fmaf(q0[9], kc0.y, dt0);  dt1 = fmaf(q1[9], kc1.y, dt1);
            const float pe0 = __expf(dt0 * inv_sqrt10);
            const float pe1 = __expf(dt1 * inv_sqrt10);
            ssum0 += pe0;
            ssum1 += pe1;
            const float* vj0 = vb0 + j * 12;
            const float4 va0 = *(const float4*)vj0;
            const float4 vb0v = *(const float4*)(vj0 + 4);
            const float2 vc0 = *(const float2*)(vj0 + 8);
            const float* vj1 = vb1 + j * 12;
            const float4 va1 = *(const float4*)vj1;
            const float4 vb1v = *(const float4*)(vj1 + 4);
            const float2 vc1 = *(const float2*)(vj1 + 8);
            ctx0[0] = fmaf(pe0, va0.x, ctx0[0]);  ctx1[0] = fmaf(pe1, va1.x, ctx1[0]);
            ctx0[1] = fmaf(pe0, va0.y, ctx0[1]);  ctx1[1] = fmaf(pe1, va1.y, ctx1[1]);
            ctx0[2] = fmaf(pe0, va0.z, ctx0[2]);  ctx1[2] = fmaf(pe1, va1.z, ctx1[2]);
            ctx0[3] = fmaf(pe0, va0.w, ctx0[3]);  ctx1[3] = fmaf(pe1, va1.w, ctx1[3]);
            ctx0[4] = fmaf(pe0, vb0v.x, ctx0[4]); ctx1[4] = fmaf(pe1, vb1v.x, ctx1[4]);
            ctx0[5] = fmaf(pe0, vb0v.y, ctx0[5]); ctx1[5] = fmaf(pe1, vb1v.y, ctx1[5]);
            ctx0[6] = fmaf(pe0, vb0v.z, ctx0[6]); ctx1[6] = fmaf(pe1, vb1v.z, ctx1[6]);
            ctx0[7] = fmaf(pe0, vb0v.w, ctx0[7]); ctx1[7] = fmaf(pe1, vb1v.w, ctx1[7]);
            ctx0[8] = fmaf(pe0, vc0.x, ctx0[8]);  ctx1[8] = fmaf(pe1, vc1.x, ctx1[8]);
            ctx0[9] = fmaf(pe0, vc0.y, ctx0[9]);  ctx1[9] = fmaf(pe1, vc1.y, ctx1[9]);
        }
        const float rs0 = __fdividef(1.f, ssum0);
        const float rs1 = __fdividef(1.f, ssum1);
        if (lane < NF) {
            float2* zs0 = (float2*)(zrow0 + tok * 10);
            float2* zs1 = (float2*)(zrow1 + tok * 10);
            #pragma unroll
            for (int u = 0; u < 5; u++) {
                zs0[u] = make_float2(fmaf(ctx0[2*u],   rs0, h0[2*u]),
                                     fmaf(ctx0[2*u+1], rs0, h0[2*u+1]));
                zs1[u] = make_float2(fmaf(ctx1[2*u],   rs1, h1[2*u]),
                                     fmaf(ctx1[2*u+1], rs1, h1[2*u+1]));
            }
        }
        if (lane == NF) {
            zrow0[230] = 0.f; zrow0[231] = 0.f;
            zrow1[230] = 0.f; zrow1[231] = 0.f;
        }
        __syncwarp();
    }
}

// ======================= Phase 2: wmma bf16 MLP + heads =================
// smem bytes: A_hi [128][240] bf16 | A_lo | B [240][176] bf16 | staging 8K
static constexpr int AHI = 0;
static constexpr int ALO = 61440;
static constexpr int BBO = 122880;
static constexpr int STG = 207360;
static constexpr int SMEM2 = 215552;

__global__ void __launch_bounds__(256, 1)
phase2_wmma(float* __restrict__ out, int B)
{
    extern __shared__ char smp[];
    __nv_bfloat16* Ah = (__nv_bfloat16*)(smp + AHI);
    __nv_bfloat16* Al = (__nv_bfloat16*)(smp + ALO);
    __nv_bfloat16* Bs = (__nv_bfloat16*)(smp + BBO);
    const int tid  = threadIdx.x;
    const int w    = tid >> 5;
    const int lane = tid & 31;
    const int rowbase = blockIdx.x * 128;
    float* stg = (float*)(smp + STG) + w * 256;

    // ---- A init from g_z: ldm 240, bias-one at k=230, zeros beyond ----
    #pragma unroll 1
    for (int i = tid; i < 128 * 120; i += 256) {
        const int m  = i / 120;
        const int k0 = (i - m * 120) * 2;
        const float* zr = g_z + (size_t)(rowbase + m) * ZS;
        const float v0 = (k0 < 230) ? zr[k0] : ((k0 == 230) ? 1.f : 0.f);
        const float v1 = (k0 + 1 < 230) ? zr[k0 + 1] : 0.f;
        uint32_t h, l;
        split2(v0, v1, h, l);
        *(uint32_t*)(Ah + m * 240 + k0) = h;
        *(uint32_t*)(Al + m * 240 + k0) = l;
    }
    __syncthreads();

    #pragma unroll 1
    for (int l = 0; l < 5; l++) {
        const int KP = (l == 0) ? 240 : 176;
        const int nk = KP / 16;
        wmma::fragment<wmma::accumulator, 16, 16, 16, float> acc[11];
        #pragma unroll
        for (int n = 0; n < 11; n++) wmma::fill_fragment(acc[n], 0.f);

        // ---- pass 1: Bh (terms Ah*Bh + Al*Bh) ----
        {
            const uint4* s4 = (const uint4*)(g_wb + wb_off(l));
            uint4* d4 = (uint4*)Bs;
            const int cnt = wb_half(l) >> 4;
            for (int i = tid; i < cnt; i += 256) d4[i] = s4[i];
        }
        __syncthreads();
        #pragma unroll 1
        for (int ks = 0; ks < nk; ks++) {
            wmma::fragment<wmma::matrix_a, 16, 16, 16, __nv_bfloat16, wmma::row_major> fa, fl;
            wmma::load_matrix_sync(fa, Ah + w * 16 * KP + ks * 16, KP);
            wmma::load_matrix_sync(fl, Al + w * 16 * KP + ks * 16, KP);
            #pragma unroll
            for (int n = 0; n < 11; n++) {
                wmma::fragment<wmma::matrix_b, 16, 16, 16, __nv_bfloat16, wmma::row_major> fb;
                wmma::load_matrix_sync(fb, Bs + ks * 16 * NP + n * 16, NP);
                wmma::mma_sync(acc[n], fa, fb, acc[n]);
                wmma::mma_sync(acc[n], fl, fb, acc[n]);
            }
        }
        __syncthreads();

        // ---- pass 2: Bl (term Ah*Bl) ----
        {
            const uint4* s4 = (const uint4*)(g_wb + wb_off(l) + wb_half(l));
            uint4* d4 = (uint4*)Bs;
            const int cnt = wb_half(l) >> 4;
            for (int i = tid; i < cnt; i += 256) d4[i] = s4[i];
        }
        __syncthreads();
        #pragma unroll 1
        for (int ks = 0; ks < nk; ks++) {
            wmma::fragment<wmma::matrix_a, 16, 16, 16, __nv_bfloat16, wmma::row_major> fa;
            wmma::load_matrix_sync(fa, Ah + w * 16 * KP + ks * 16, KP);
            #pragma unroll
            for (int n = 0; n < 11; n++) {
                wmma::fragment<wmma::matrix_b, 16, 16, 16, __nv_bfloat16, wmma::row_major> fb;
                wmma::load_matrix_sync(fb, Bs + ks * 16 * NP + n * 16, NP);
                wmma::mma_sync(acc[n], fa, fb, acc[n]);
            }
        }
        __syncthreads();

        // ---- epilogue ----
        const int r  = lane >> 1;
        const int c0 = (lane & 1) * 8;
        if (l < 4) {
            // ReLU + split -> next-layer A (ldm 176), bias-one at k=164
            #pragma unroll 1
            for (int n = 0; n < 11; n++) {
                wmma::store_matrix_sync(stg, acc[n], 16, wmma::mem_row_major);
                __syncwarp();
                float v[8];
                #pragma unroll
                for (int j = 0; j < 8; j++) {
                    const int k = n * 16 + c0 + j;
                    const float x = stg[r * 16 + c0 + j];
                    v[j] = (k < 164) ? fmaxf(x, 0.f) : ((k == 164) ? 1.f : 0.f);
                }
                uint32_t hh[4], ll[4];
                #pragma unroll
                for (int p = 0; p < 4; p++) split2(v[2*p], v[2*p+1], hh[p], ll[p]);
                const int m = w * 16 + r;
                *(uint4*)(Ah + m * 176 + n * 16 + c0) = make_uint4(hh[0], hh[1], hh[2], hh[3]);
                *(uint4*)(Al + m * 176 + n * 16 + c0) = make_uint4(ll[0], ll[1], ll[2], ll[3]);
                __syncwarp();
            }
        } else {
            // final z (fp32, ReLU) into A region for fp32 heads
            float* za = (float*)smp;   // [128][168] stride 168
            #pragma unroll 1
            for (int n = 0; n < 11; n++) {
                wmma::store_matrix_sync(stg, acc[n], 16, wmma::mem_row_major);
                __syncwarp();
                const int m = w * 16 + r;
                #pragma unroll
                for (int j = 0; j < 8; j++) {
                    const int k = n * 16 + c0 + j;
                    if (k < 164)
                        za[m * 168 + k] = fmaxf(stg[r * 16 + c0 + j], 0.f);
                }
                __syncwarp();
            }
        }
        __syncthreads();
    }

    // ---- heads: move[5] + mark[1], fp32 ----
    {
        float* za  = (float*)smp;
        float* whs = (float*)(smp + STG);    // [k][6]
        for (int i = tid; i < 1008; i += 256) {
            const int o = i / 168, k = i - o * 168;
            whs[k * 6 + o] = g_wh[i];
        }
        __syncthreads();
        const int r = tid >> 1;
        const int g = tid & 1;
        const float* zr = za + r * 168;
        float a0 = g_bh[g * 3 + 0];
        float a1 = g_bh[g * 3 + 1];
        float a2 = g_bh[g * 3 + 2];
        #pragma unroll 4
        for (int k = 0; k < 164; k++) {
            const float v = zr[k];
            const float* wk = whs + k * 6 + g * 3;
            a0 = fmaf(v, wk[0], a0);
            a1 = fmaf(v, wk[1], a1);
            a2 = fmaf(v, wk[2], a2);
        }
        const int row = rowbase + r;
        if (g == 0) {
            out[row * 5 + 0] = a0;
            out[row * 5 + 1] = a1;
            out[row * 5 + 2] = a2;
        } else {
            out[row * 5 + 3] = a0;
            out[row * 5 + 4] = a1;
            out[(long long)B * 5 + row] = a2;
        }
    }
}

extern "C" void kernel_launch(void* const* d_in, const int* in_sizes, int n_in,
                              void* d_out, int out_size) {
    const float* x   = (const float*)d_in[0];
    const float* Wp  = (const float*)d_in[1];
    const float* bp  = (const float*)d_in[2];
    const float* Wq  = (const float*)d_in[3];
    const float* Wk  = (const float*)d_in[4];
    const float* Wv  = (const float*)d_in[5];
    const float* W1  = (const float*)d_in[6];
    const float* b1  = (const float*)d_in[7];
    const float* W2  = (const float*)d_in[8];
    const float* b2  = (const float*)d_in[9];
    const float* W3  = (const float*)d_in[10];
    const float* b3  = (const float*)d_in[11];
    const float* W4  = (const float*)d_in[12];
    const float* b4  = (const float*)d_in[13];
    const float* W5  = (const float*)d_in[14];
    const float* b5  = (const float*)d_in[15];
    const float* Wm  = (const float*)d_in[16];
    const float* bm  = (const float*)d_in[17];
    const float* Wmk = (const float*)d_in[18];
    const float* bmk = (const float*)d_in[19];
    float* out = (float*)d_out;

    const int B = in_sizes[0] / OBS;

    cudaFuncSetAttribute(phase2_wmma,
                         cudaFuncAttributeMaxDynamicSharedMemorySize, SMEM2);

    pack_misc<<<dim3(232, 3), 192>>>(Wm, bm, Wmk, bmk, Wp, Wq, Wk, Wv);
    pack_wb<<<dim3(240, 10), 176>>>(W1, W2, W3, W4, W5, b1, b2, b3, b4, b5);
    phase1_kernel<<<B / 32, 256>>>(x, bp, B);
    phase2_wmma<<<B / 128, 256, SMEM2>>>(out, B);
}